// round 15
// baseline (speedup 1.0000x reference)
#include <cuda_runtime.h>
#include <cuda_fp16.h>
#include <cstdint>

#define IMG 224
#define HW  (IMG * IMG)        // 50176
#define WX  42                 // staged window width (even -> float2 loads)
#define SX  43                 // smem row stride in 8B slots (ODD -> bank-free)
#define YH  41                 // staged window rows (32+4+4+1)
#define PLANE (SX * YH)        // 1763 slots per image
#define NJ  (YH * (WX / 2))    // 861 two-site staging jobs
#define NT  512

// packed site: p01 = half2(ch0, ch1), p2x = half2(ch2, 0) — 8 bytes
struct __align__(8) Site {
    __half2 p01;
    __half2 p2x;
};

__global__ __launch_bounds__(NT, 4) void vm_kernel(
    const float* __restrict__ im1, const float* __restrict__ im2,
    const float* __restrict__ C,   const float* __restrict__ M1,
    const float* __restrict__ M2,  float* __restrict__ out)
{
    __shared__ __align__(16) Site rgb[2 * PLANE];   // 28208 B

    const int tid = threadIdx.x;
    const int l   = tid & 31;            // lane: y within tile
    const int w   = tid >> 5;            // warp: x pair {X0+w, X0+w+16}
    const int X0 = blockIdx.x * 32;
    const int Y0 = blockIdx.y * 32;
    const int n  = blockIdx.z;

    const float* b1 = im1 + n * 3 * HW;
    const float* b2 = im2 + n * 3 * HW;

    // staged window fully inside the image; sx0 EVEN in all cases
    // (X0-4 ≡ 28 mod 32, clamps 0 and IMG-WX=182 are even) -> 8B-aligned rows
    const int sx0 = min(max(X0 - 4, 0), IMG - WX);
    const int sy0 = min(max(Y0 - 4, 0), IMG - YH);

    // ── staging: float2 LDG -> fp16 pack -> 2x STS.64 per image, 861 jobs ──
    {
        const float* g1base = b1 + sy0 * IMG + sx0;
        const float* g2base = b2 + sy0 * IMG + sx0;
#pragma unroll
        for (int jj = 0; jj < 2; jj++) {
            int j = tid + jj * NT;
            if (j < NJ) {
                int r = j / 21;              // 21 float2 pairs per row
                int k = j - r * 21;
                int g = r * IMG + 2 * k;
                int si = r * SX + 2 * k;
                {
                    const float* G = g1base + g;
                    float2 a0 = __ldg((const float2*)(G));
                    float2 a1 = __ldg((const float2*)(G + HW));
                    float2 a2 = __ldg((const float2*)(G + 2 * HW));
                    Site sA, sB;
                    sA.p01 = __floats2half2_rn(a0.x, a1.x);
                    sA.p2x = __floats2half2_rn(a2.x, 0.0f);
                    sB.p01 = __floats2half2_rn(a0.y, a1.y);
                    sB.p2x = __floats2half2_rn(a2.y, 0.0f);
                    rgb[si]     = sA;
                    rgb[si + 1] = sB;
                }
                {
                    const float* G = g2base + g;
                    float2 a0 = __ldg((const float2*)(G));
                    float2 a1 = __ldg((const float2*)(G + HW));
                    float2 a2 = __ldg((const float2*)(G + 2 * HW));
                    Site sA, sB;
                    sA.p01 = __floats2half2_rn(a0.x, a1.x);
                    sA.p2x = __floats2half2_rn(a2.x, 0.0f);
                    sB.p01 = __floats2half2_rn(a0.y, a1.y);
                    sB.p2x = __floats2half2_rn(a2.y, 0.0f);
                    rgb[PLANE + si]     = sA;
                    rgb[PLANE + si + 1] = sB;
                }
            }
        }
    }

    // ── coalesced C/M loads for both pixels (overlap staging latency) ──
    const int y  = Y0 + l;
    const int i0 = (X0 + w) * IMG + y;
    const int i1 = i0 + 16 * IMG;
    float Cxs[2], Cys[2], m1s[2], m2s[2];
    Cxs[0] = __ldg(C  + (n * 2) * HW + i0);
    Cys[0] = __ldg(C  + (n * 2 + 1) * HW + i0);
    m1s[0] = __ldg(M1 + n * HW + i0);
    m2s[0] = __ldg(M2 + n * HW + i0);
    Cxs[1] = __ldg(C  + (n * 2) * HW + i1);
    Cys[1] = __ldg(C  + (n * 2 + 1) * HW + i1);
    m1s[1] = __ldg(M1 + n * HW + i1);
    m2s[1] = __ldg(M2 + n * HW + i1);

    const float fyv  = (float)y;
    const float sx0f = (float)sx0, sy0f = (float)sy0;
    const float lox = sx0f, hix = (float)(sx0 + WX - 1);
    const float loy = sy0f, hiy = (float)(sy0 + YH - 1);

    __syncthreads();

    float* outn = out + n * 3 * HW;

#pragma unroll
    for (int t = 0; t < 2; t++) {
        const float fxv = (float)(X0 + w + 16 * t);
        const float Cx = Cxs[t], Cy = Cys[t];
        const float m1v = m1s[t], m2v = m2s[t];

        float res[3];
#pragma unroll
        for (int s = 0; s < 2; s++) {
            const float px = s ? (fxv - Cx) : (fxv + Cx);
            const float py = s ? (fyv - Cy) : (fyv + Cy);

            float fx = floorf(px), cx = ceilf(px);
            float fy = floorf(py), cy = ceilf(py);
            float wfx = 1.0f - (px - fx);
            float wcx = 1.0f - (cx - px);
            float wfy = 1.0f - (py - fy);
            float wcy = 1.0f - (cy - py);
            float wff = wfx * wfy, wcf = wcx * wfy;
            float wfc = wfx * wcy, wcc = wcx * wcy;

            float v0, v1, v2;
            if (fx >= lox && cx <= hix && fy >= loy && cy <= hiy) {
                // window ⊂ image → taps in-image → reference's flat-index
                // truncate/clip is a no-op; exact float-domain indices (<2^24)
                float dcf  = cx - fx;                    // 0 or 1
                float drf  = cy - fy;                    // 0 or 1
                float t00f = fmaf(fy - sy0f, (float)SX, fx - sx0f);
                float t10f = fmaf(drf, (float)SX, t00f);
                int t00 = (int)t00f;
                int t01 = (int)(t00f + dcf);
                int t10 = (int)t10f;
                int t11 = (int)(t10f + dcf);

                const Site* pp = rgb + s * PLANE;
                Site r00 = pp[t00];
                Site r01 = pp[t01];
                Site r10 = pp[t10];
                Site r11 = pp[t11];

                // half2 4-tap accumulation (weights broadcast to half2)
                __half2 hff = __float2half2_rn(wff);
                __half2 hcf = __float2half2_rn(wcf);
                __half2 hfc = __float2half2_rn(wfc);
                __half2 hcc = __float2half2_rn(wcc);

                __half2 acc01 = __hmul2(hff, r00.p01);
                acc01 = __hfma2(hcf, r01.p01, acc01);
                acc01 = __hfma2(hfc, r10.p01, acc01);
                acc01 = __hfma2(hcc, r11.p01, acc01);
                __half2 acc2 = __hmul2(hff, r00.p2x);
                acc2 = __hfma2(hcf, r01.p2x, acc2);
                acc2 = __hfma2(hfc, r10.p2x, acc2);
                acc2 = __hfma2(hcc, r11.p2x, acc2);

                float2 v01 = __half22float2(acc01);
                v0 = v01.x;
                v1 = v01.y;
                v2 = __low2float(acc2);
            } else {
                // exact fp32 reference fallback:
                // ind = clip(int32(nx + 224*ny), 0, HW-1)
                const float* gim = s ? b2 : b1;
                int iff = (int)(fx + 224.0f * fy);
                int icf = (int)(cx + 224.0f * fy);
                int ifc = (int)(fx + 224.0f * cy);
                int icc = (int)(cx + 224.0f * cy);
                iff = min(max(iff, 0), HW - 1);
                icf = min(max(icf, 0), HW - 1);
                ifc = min(max(ifc, 0), HW - 1);
                icc = min(max(icc, 0), HW - 1);
                float acc[3];
#pragma unroll
                for (int ch = 0; ch < 3; ch++) {
                    const float* p = gim + ch * HW;
                    float v = wff * __ldg(p + iff);
                    v = fmaf(wcf, __ldg(p + icf), v);
                    v = fmaf(wfc, __ldg(p + ifc), v);
                    v = fmaf(wcc, __ldg(p + icc), v);
                    acc[ch] = v;
                }
                v0 = acc[0]; v1 = acc[1]; v2 = acc[2];
            }
            if (s == 0) { res[0] = v0 * m1v; res[1] = v1 * m1v; res[2] = v2 * m1v; }
            else        { res[0] = fmaf(v0, m2v, res[0]);
                          res[1] = fmaf(v1, m2v, res[1]);
                          res[2] = fmaf(v2, m2v, res[2]); }
        }

        const int i = (t == 0) ? i0 : i1;
#pragma unroll
        for (int ch = 0; ch < 3; ch++)
            outn[ch * HW + i] = res[ch];
    }
}

extern "C" void kernel_launch(void* const* d_in, const int* in_sizes, int n_in,
                              void* d_out, int out_size)
{
    const float* im1 = (const float*)d_in[0];
    const float* im2 = (const float*)d_in[1];
    const float* C   = (const float*)d_in[2];
    const float* M1  = (const float*)d_in[3];
    const float* M2  = (const float*)d_in[4];
    float* out = (float*)d_out;

    dim3 block(NT, 1, 1);
    dim3 grid(7, 7, 64);   // 3136 blocks, 32x32 px each
    vm_kernel<<<grid, block>>>(im1, im2, C, M1, M2, out);
}

// round 16
// speedup vs baseline: 1.0499x; 1.0499x over previous
#include <cuda_runtime.h>
#include <cuda_fp16.h>
#include <cstdint>

#define IMG 224
#define HW  (IMG * IMG)        // 50176
#define WX  44                 // staged window width (mult-4 -> float4 loads)
#define SX  45                 // smem row stride in 8B slots (ODD -> bank-free)
#define YH  41                 // staged window rows (32+4+4+1)
#define PLANE (SX * YH)        // 1845 slots per image
#define NJ  (YH * (WX / 4))    // 451 four-site staging jobs (single pass)
#define NT  512

// packed site: p01 = half2(ch0, ch1), p2x = half2(ch2, 0) — 8 bytes
struct __align__(8) Site {
    __half2 p01;
    __half2 p2x;
};

__global__ __launch_bounds__(NT, 4) void vm_kernel(
    const float* __restrict__ im1, const float* __restrict__ im2,
    const float* __restrict__ C,   const float* __restrict__ M1,
    const float* __restrict__ M2,  float* __restrict__ out)
{
    __shared__ __align__(16) Site rgb[2 * PLANE];   // 29520 B

    const int tid = threadIdx.x;
    const int l   = tid & 31;            // lane: y within tile
    const int w   = tid >> 5;            // warp: x pair {X0+w, X0+w+16}
    const int X0 = blockIdx.x * 32;
    const int Y0 = blockIdx.y * 32;
    const int n  = blockIdx.z;

    const float* b1 = im1 + n * 3 * HW;
    const float* b2 = im2 + n * 3 * HW;

    // staged window fully inside the image; sx0 is a multiple of 4 in all
    // cases (X0-4 ≡ 28 mod 32; clamps 0 and IMG-WX=180) -> 16B-aligned rows
    const int sx0 = min(max(X0 - 4, 0), IMG - WX);
    const int sy0 = min(max(Y0 - 4, 0), IMG - YH);

    // ── coalesced C/M loads for both pixels (issued first, long latency) ──
    const int y  = Y0 + l;
    const int i0 = (X0 + w) * IMG + y;
    const int i1 = i0 + 16 * IMG;
    float Cxs[2], Cys[2], m1s[2], m2s[2];
    Cxs[0] = __ldg(C  + (n * 2) * HW + i0);
    Cys[0] = __ldg(C  + (n * 2 + 1) * HW + i0);
    m1s[0] = __ldg(M1 + n * HW + i0);
    m2s[0] = __ldg(M2 + n * HW + i0);
    Cxs[1] = __ldg(C  + (n * 2) * HW + i1);
    Cys[1] = __ldg(C  + (n * 2 + 1) * HW + i1);
    m1s[1] = __ldg(M1 + n * HW + i1);
    m2s[1] = __ldg(M2 + n * HW + i1);

    // ── staging: float4 LDG -> fp16 pack -> 4x STS.64 per image; one pass ──
    if (tid < NJ) {
        int r = tid / 11;                // 11 float4 quads per row
        int k = tid - r * 11;
        int g  = r * IMG + 4 * k;
        int si = r * SX + 4 * k;
        const float* g1base = b1 + sy0 * IMG + sx0;
        const float* g2base = b2 + sy0 * IMG + sx0;
        {
            const float* G = g1base + g;
            float4 a0 = __ldg((const float4*)(G));
            float4 a1 = __ldg((const float4*)(G + HW));
            float4 a2 = __ldg((const float4*)(G + 2 * HW));
            Site s0, s1, s2, s3;
            s0.p01 = __floats2half2_rn(a0.x, a1.x);
            s0.p2x = __floats2half2_rn(a2.x, 0.0f);
            s1.p01 = __floats2half2_rn(a0.y, a1.y);
            s1.p2x = __floats2half2_rn(a2.y, 0.0f);
            s2.p01 = __floats2half2_rn(a0.z, a1.z);
            s2.p2x = __floats2half2_rn(a2.z, 0.0f);
            s3.p01 = __floats2half2_rn(a0.w, a1.w);
            s3.p2x = __floats2half2_rn(a2.w, 0.0f);
            rgb[si]     = s0;
            rgb[si + 1] = s1;
            rgb[si + 2] = s2;
            rgb[si + 3] = s3;
        }
        {
            const float* G = g2base + g;
            float4 a0 = __ldg((const float4*)(G));
            float4 a1 = __ldg((const float4*)(G + HW));
            float4 a2 = __ldg((const float4*)(G + 2 * HW));
            Site s0, s1, s2, s3;
            s0.p01 = __floats2half2_rn(a0.x, a1.x);
            s0.p2x = __floats2half2_rn(a2.x, 0.0f);
            s1.p01 = __floats2half2_rn(a0.y, a1.y);
            s1.p2x = __floats2half2_rn(a2.y, 0.0f);
            s2.p01 = __floats2half2_rn(a0.z, a1.z);
            s2.p2x = __floats2half2_rn(a2.z, 0.0f);
            s3.p01 = __floats2half2_rn(a0.w, a1.w);
            s3.p2x = __floats2half2_rn(a2.w, 0.0f);
            rgb[PLANE + si]     = s0;
            rgb[PLANE + si + 1] = s1;
            rgb[PLANE + si + 2] = s2;
            rgb[PLANE + si + 3] = s3;
        }
    }

    const float fyv  = (float)y;
    const float sx0f = (float)sx0, sy0f = (float)sy0;
    const float lox = sx0f, hix = (float)(sx0 + WX - 1);
    const float loy = sy0f, hiy = (float)(sy0 + YH - 1);

    __syncthreads();

    float* outn = out + n * 3 * HW;

#pragma unroll
    for (int t = 0; t < 2; t++) {
        const float fxv = (float)(X0 + w + 16 * t);
        const float Cx = Cxs[t], Cy = Cys[t];
        const float m1v = m1s[t], m2v = m2s[t];

        float res[3];
#pragma unroll
        for (int s = 0; s < 2; s++) {
            const float px = s ? (fxv - Cx) : (fxv + Cx);
            const float py = s ? (fyv - Cy) : (fyv + Cy);

            float fx = floorf(px), cx = ceilf(px);
            float fy = floorf(py), cy = ceilf(py);
            float wfx = 1.0f - (px - fx);
            float wcx = 1.0f - (cx - px);
            float wfy = 1.0f - (py - fy);
            float wcy = 1.0f - (cy - py);
            float wff = wfx * wfy, wcf = wcx * wfy;
            float wfc = wfx * wcy, wcc = wcx * wcy;

            float v0, v1, v2;
            if (fx >= lox && cx <= hix && fy >= loy && cy <= hiy) {
                // window ⊂ image → taps in-image → reference's flat-index
                // truncate/clip is a no-op; exact float-domain indices (<2^24)
                float dcf  = cx - fx;                    // 0 or 1
                float drf  = cy - fy;                    // 0 or 1
                float t00f = fmaf(fy - sy0f, (float)SX, fx - sx0f);
                float t10f = fmaf(drf, (float)SX, t00f);
                int t00 = (int)t00f;
                int t01 = (int)(t00f + dcf);
                int t10 = (int)t10f;
                int t11 = (int)(t10f + dcf);

                const Site* pp = rgb + s * PLANE;
                Site r00 = pp[t00];
                Site r01 = pp[t01];
                Site r10 = pp[t10];
                Site r11 = pp[t11];

                float2 a00 = __half22float2(r00.p01);
                float2 a01 = __half22float2(r01.p01);
                float2 a10 = __half22float2(r10.p01);
                float2 a11 = __half22float2(r11.p01);
                float  c00 = __low2float(r00.p2x);
                float  c01 = __low2float(r01.p2x);
                float  c10 = __low2float(r10.p2x);
                float  c11 = __low2float(r11.p2x);

                v0 = wff * a00.x;
                v0 = fmaf(wcf, a01.x, v0);
                v0 = fmaf(wfc, a10.x, v0);
                v0 = fmaf(wcc, a11.x, v0);
                v1 = wff * a00.y;
                v1 = fmaf(wcf, a01.y, v1);
                v1 = fmaf(wfc, a10.y, v1);
                v1 = fmaf(wcc, a11.y, v1);
                v2 = wff * c00;
                v2 = fmaf(wcf, c01, v2);
                v2 = fmaf(wfc, c10, v2);
                v2 = fmaf(wcc, c11, v2);
            } else {
                // exact fp32 reference fallback:
                // ind = clip(int32(nx + 224*ny), 0, HW-1)
                const float* gim = s ? b2 : b1;
                int iff = (int)(fx + 224.0f * fy);
                int icf = (int)(cx + 224.0f * fy);
                int ifc = (int)(fx + 224.0f * cy);
                int icc = (int)(cx + 224.0f * cy);
                iff = min(max(iff, 0), HW - 1);
                icf = min(max(icf, 0), HW - 1);
                ifc = min(max(ifc, 0), HW - 1);
                icc = min(max(icc, 0), HW - 1);
                float acc[3];
#pragma unroll
                for (int ch = 0; ch < 3; ch++) {
                    const float* p = gim + ch * HW;
                    float v = wff * __ldg(p + iff);
                    v = fmaf(wcf, __ldg(p + icf), v);
                    v = fmaf(wfc, __ldg(p + ifc), v);
                    v = fmaf(wcc, __ldg(p + icc), v);
                    acc[ch] = v;
                }
                v0 = acc[0]; v1 = acc[1]; v2 = acc[2];
            }
            if (s == 0) { res[0] = v0 * m1v; res[1] = v1 * m1v; res[2] = v2 * m1v; }
            else        { res[0] = fmaf(v0, m2v, res[0]);
                          res[1] = fmaf(v1, m2v, res[1]);
                          res[2] = fmaf(v2, m2v, res[2]); }
        }

        const int i = (t == 0) ? i0 : i1;
#pragma unroll
        for (int ch = 0; ch < 3; ch++)
            outn[ch * HW + i] = res[ch];
    }
}

extern "C" void kernel_launch(void* const* d_in, const int* in_sizes, int n_in,
                              void* d_out, int out_size)
{
    const float* im1 = (const float*)d_in[0];
    const float* im2 = (const float*)d_in[1];
    const float* C   = (const float*)d_in[2];
    const float* M1  = (const float*)d_in[3];
    const float* M2  = (const float*)d_in[4];
    float* out = (float*)d_out;

    dim3 block(NT, 1, 1);
    dim3 grid(7, 7, 64);   // 3136 blocks, 32x32 px each
    vm_kernel<<<grid, block>>>(im1, im2, C, M1, M2, out);
}